// round 2
// baseline (speedup 1.0000x reference)
#include <cuda_runtime.h>

#define BB 8
#define TT 2048
#define CC 1024
#define HH 64
#define MM (BB*TT)   // 16384

// scratch for q, k, v (4 MB each) — __device__ globals per allocation rules
__device__ float g_q[MM*HH];
__device__ float g_k[MM*HH];
__device__ float g_v[MM*HH];

// ---------------------------------------------------------------------------
// Kernel 1: fused QKV projection. out[m][n] = sum_k x[m][k] * W[k][n]
// M=16384, K=1024, N=64.  BM=64, BN=64(=H), BK=16. 256 threads, 4x4/thread.
// Already ~90% of fp32 FMA roofline — unchanged this round.
// ---------------------------------------------------------------------------
__global__ __launch_bounds__(256) void qkv_gemm(
    const float* __restrict__ x,
    const float* __restrict__ Wq,
    const float* __restrict__ Wk,
    const float* __restrict__ Wv)
{
    __shared__ float As[16][68];
    __shared__ float Bs[16][64];

    const float* W   = (blockIdx.y == 0) ? Wq : ((blockIdx.y == 1) ? Wk : Wv);
    float*       out = (blockIdx.y == 0) ? g_q : ((blockIdx.y == 1) ? g_k : g_v);

    const int m0  = blockIdx.x * 64;
    const int tid = threadIdx.x;
    const int tx  = tid & 15;
    const int ty  = tid >> 4;

    const int lrow  = tid >> 2;
    const int lquad = tid & 3;
    const int bk = tid >> 4;
    const int bq = tid & 15;

    float acc[4][4] = {};

    for (int k0 = 0; k0 < CC; k0 += 16) {
        float4 av = *(const float4*)&x[(size_t)(m0 + lrow) * CC + k0 + lquad * 4];
        As[lquad*4 + 0][lrow] = av.x;
        As[lquad*4 + 1][lrow] = av.y;
        As[lquad*4 + 2][lrow] = av.z;
        As[lquad*4 + 3][lrow] = av.w;
        *(float4*)&Bs[bk][bq*4] = *(const float4*)&W[(size_t)(k0 + bk) * HH + bq * 4];
        __syncthreads();

        #pragma unroll
        for (int k = 0; k < 16; k++) {
            float4 a4 = *(const float4*)&As[k][ty*4];
            float4 b4 = *(const float4*)&Bs[k][tx*4];
            float a[4] = {a4.x, a4.y, a4.z, a4.w};
            float b[4] = {b4.x, b4.y, b4.z, b4.w};
            #pragma unroll
            for (int i = 0; i < 4; i++)
                #pragma unroll
                for (int j = 0; j < 4; j++)
                    acc[i][j] += a[i] * b[j];
        }
        __syncthreads();
    }

    #pragma unroll
    for (int i = 0; i < 4; i++) {
        float4 v = make_float4(acc[i][0], acc[i][1], acc[i][2], acc[i][3]);
        *(float4*)&out[(size_t)(m0 + ty*4 + i) * HH + tx*4] = v;
    }
}

// ---------------------------------------------------------------------------
// Kernel 2: causal flash attention, 4 threads per query row.
// grid = (T/64, B), 256 threads/block. tid = qid*4 + sub; sub owns dims
// [sub*16, sub*16+16). Scores reduced across the 4 sub-lanes via shfl.xor.
// Online softmax per 16-key group; scores live in registers (no Ps smem).
// smem = 32 KB (K+V tiles only).
// ---------------------------------------------------------------------------
__global__ __launch_bounds__(256) void attn(float* __restrict__ out)
{
    __shared__ float Ks[64][64];
    __shared__ float Vs[64][64];

    const int b   = blockIdx.y;
    const int qt  = (gridDim.x - 1) - blockIdx.x;   // heavy tiles first
    const int q0  = qt * 64;
    const int tid = threadIdx.x;
    const int qid = tid >> 2;          // 0..63  query within tile
    const int sub = tid & 3;           // 0..3   head-dim quarter
    const int row = q0 + qid;
    const int dbase = sub * 16;
    const float scale = 0.03125f;      // C^-0.5 = 1/32

    // my 16 dims of the query row, pre-scaled
    float q[16];
    {
        const float* qrow = &g_q[((size_t)b * TT + row) * HH + dbase];
        #pragma unroll
        for (int d = 0; d < 16; d += 4) {
            float4 v = *(const float4*)&qrow[d];
            q[d+0] = v.x * scale; q[d+1] = v.y * scale;
            q[d+2] = v.z * scale; q[d+3] = v.w * scale;
        }
    }

    float o[16];
    #pragma unroll
    for (int d = 0; d < 16; d++) o[d] = 0.f;
    float m = -1e30f, l = 0.f;

    const int nTiles = qt + 1;
    for (int t = 0; t < nTiles; t++) {
        const int k0 = t * 64;
        // cooperative coalesced load of K, V tiles: 1024 float4 each, 4/thread
        {
            const float4* kb = (const float4*)&g_k[((size_t)b * TT + k0) * HH];
            const float4* vb = (const float4*)&g_v[((size_t)b * TT + k0) * HH];
            float4* ks = (float4*)&Ks[0][0];
            float4* vs = (float4*)&Vs[0][0];
            #pragma unroll
            for (int i = 0; i < 4; i++) {
                int idx = i * 256 + tid;
                ks[idx] = kb[idx];
                vs[idx] = vb[idx];
            }
        }
        __syncthreads();

        // 4 groups of 16 keys; online softmax per group
        #pragma unroll
        for (int g = 0; g < 4; g++) {
            const int jbase = g * 16;
            float s[16];
            #pragma unroll
            for (int j = 0; j < 16; j++) {
                float a0 = 0.f, a1 = 0.f, a2 = 0.f, a3 = 0.f;
                const float4* kr = (const float4*)&Ks[jbase + j][dbase];
                #pragma unroll
                for (int d4 = 0; d4 < 4; d4++) {
                    float4 kv = kr[d4];
                    a0 += q[d4*4+0] * kv.x;
                    a1 += q[d4*4+1] * kv.y;
                    a2 += q[d4*4+2] * kv.z;
                    a3 += q[d4*4+3] * kv.w;
                }
                float part = (a0 + a1) + (a2 + a3);
                part += __shfl_xor_sync(0xFFFFFFFF, part, 1);
                part += __shfl_xor_sync(0xFFFFFFFF, part, 2);
                s[j] = (k0 + jbase + j > row) ? -1e30f : part;
            }

            float mt = s[0];
            #pragma unroll
            for (int j = 1; j < 16; j++) mt = fmaxf(mt, s[j]);
            const float mnew = fmaxf(m, mt);
            const float corr = __expf(m - mnew);
            l *= corr;
            #pragma unroll
            for (int d = 0; d < 16; d++) o[d] *= corr;

            #pragma unroll
            for (int j = 0; j < 16; j++) {
                float p = __expf(s[j] - mnew);
                l += p;
                const float4* vr = (const float4*)&Vs[jbase + j][dbase];
                #pragma unroll
                for (int d4 = 0; d4 < 4; d4++) {
                    float4 vv = vr[d4];
                    o[d4*4+0] += p * vv.x;
                    o[d4*4+1] += p * vv.y;
                    o[d4*4+2] += p * vv.z;
                    o[d4*4+3] += p * vv.w;
                }
            }
            m = mnew;
        }
        __syncthreads();
    }

    const float inv = 1.f / l;
    float* orow = &out[((size_t)b * TT + row) * HH + dbase];
    #pragma unroll
    for (int d = 0; d < 16; d += 4) {
        float4 v = make_float4(o[d]*inv, o[d+1]*inv, o[d+2]*inv, o[d+3]*inv);
        *(float4*)&orow[d] = v;
    }
}

// ---------------------------------------------------------------------------
extern "C" void kernel_launch(void* const* d_in, const int* in_sizes, int n_in,
                              void* d_out, int out_size)
{
    const float* x  = (const float*)d_in[0];
    const float* Wq = (const float*)d_in[1];
    const float* Wk = (const float*)d_in[2];
    const float* Wv = (const float*)d_in[3];
    float* out = (float*)d_out;

    dim3 g1(MM / 64, 3);
    qkv_gemm<<<g1, 256>>>(x, Wq, Wk, Wv);

    dim3 g2(TT / 64, BB);
    attn<<<g2, 256>>>(out);
}

// round 4
// speedup vs baseline: 2.5216x; 2.5216x over previous
#include <cuda_runtime.h>

#define BB 8
#define TT 2048
#define CC 1024
#define HH 64
#define MM (BB*TT)   // 16384

// scratch for q, k, v (4 MB each) — __device__ globals per allocation rules
__device__ float g_q[MM*HH];
__device__ float g_k[MM*HH];
__device__ float g_v[MM*HH];

// ---------------------------------------------------------------------------
// Kernel 1: fused QKV projection (at fp32 FMA roofline — unchanged).
// ---------------------------------------------------------------------------
__global__ __launch_bounds__(256) void qkv_gemm(
    const float* __restrict__ x,
    const float* __restrict__ Wq,
    const float* __restrict__ Wk,
    const float* __restrict__ Wv)
{
    __shared__ float As[16][68];
    __shared__ float Bs[16][64];

    const float* W   = (blockIdx.y == 0) ? Wq : ((blockIdx.y == 1) ? Wk : Wv);
    float*       out = (blockIdx.y == 0) ? g_q : ((blockIdx.y == 1) ? g_k : g_v);

    const int m0  = blockIdx.x * 64;
    const int tid = threadIdx.x;
    const int tx  = tid & 15;
    const int ty  = tid >> 4;

    const int lrow  = tid >> 2;
    const int lquad = tid & 3;
    const int bk = tid >> 4;
    const int bq = tid & 15;

    float acc[4][4] = {};

    for (int k0 = 0; k0 < CC; k0 += 16) {
        float4 av = *(const float4*)&x[(size_t)(m0 + lrow) * CC + k0 + lquad * 4];
        As[lquad*4 + 0][lrow] = av.x;
        As[lquad*4 + 1][lrow] = av.y;
        As[lquad*4 + 2][lrow] = av.z;
        As[lquad*4 + 3][lrow] = av.w;
        *(float4*)&Bs[bk][bq*4] = *(const float4*)&W[(size_t)(k0 + bk) * HH + bq * 4];
        __syncthreads();

        #pragma unroll
        for (int k = 0; k < 16; k++) {
            float4 a4 = *(const float4*)&As[k][ty*4];
            float4 b4 = *(const float4*)&Bs[k][tx*4];
            float a[4] = {a4.x, a4.y, a4.z, a4.w};
            float b[4] = {b4.x, b4.y, b4.z, b4.w};
            #pragma unroll
            for (int i = 0; i < 4; i++)
                #pragma unroll
                for (int j = 0; j < 4; j++)
                    acc[i][j] += a[i] * b[j];
        }
        __syncthreads();
    }

    #pragma unroll
    for (int i = 0; i < 4; i++) {
        float4 v = make_float4(acc[i][0], acc[i][1], acc[i][2], acc[i][3]);
        *(float4*)&out[(size_t)(m0 + ty*4 + i) * HH + tx*4] = v;
    }
}

// ---------------------------------------------------------------------------
// Kernel 2: causal flash attention as two register-tiled 64x64x64 GEMMs/tile.
// Dynamic smem layout (floats):
//   Qs [64][64]  : Q transposed [d][row]
//   KP [64][68]  : union — K transposed [d][col] during S, then P [j][row]
//   Vs [64][64]  : V row-major [j][n]
// 256 threads; thread (ty,tx) owns S/O rows ty*4..+3, cols tx*4..+3.
// ---------------------------------------------------------------------------
#define QS_OFF 0
#define KP_OFF 4096            // 64*64
#define VS_OFF (4096 + 4352)   // + 64*68
#define ATTN_SMEM_FLOATS (4096 + 4352 + 4096)
#define ATTN_SMEM_BYTES (ATTN_SMEM_FLOATS * 4)

__global__ __launch_bounds__(256) void attn(float* __restrict__ out)
{
    extern __shared__ float sm[];
    float* Qs = sm + QS_OFF;   // [d][row], stride 64
    float* KP = sm + KP_OFF;   // stride 68
    float* Vs = sm + VS_OFF;   // [j][n], stride 64

    const int b   = blockIdx.y;
    const int qt  = (gridDim.x - 1) - blockIdx.x;   // heavy tiles first
    const int q0  = qt * 64;
    const int tid = threadIdx.x;
    const int tx  = tid & 15;
    const int ty  = tid >> 4;
    const float scale = 0.03125f;  // C^-0.5

    // transposed, pre-scaled load of Q tile: Qs[d][r]
    {
        const int r  = tid & 63;
        const int dq = tid >> 6;   // 0..3
        const float* qrow = &g_q[((size_t)b * TT + q0 + r) * HH + dq * 16];
        #pragma unroll
        for (int u = 0; u < 4; u++) {
            float4 v = *(const float4*)&qrow[u * 4];
            Qs[(dq*16 + u*4 + 0) * 64 + r] = v.x * scale;
            Qs[(dq*16 + u*4 + 1) * 64 + r] = v.y * scale;
            Qs[(dq*16 + u*4 + 2) * 64 + r] = v.z * scale;
            Qs[(dq*16 + u*4 + 3) * 64 + r] = v.w * scale;
        }
    }

    float o[4][4] = {};
    float m[4], l[4];
    #pragma unroll
    for (int i = 0; i < 4; i++) { m[i] = -1e30f; l[i] = 0.f; }

    for (int t = 0; t <= qt; t++) {
        const int k0 = t * 64;
        // stage K transposed (into KP) + V row-major
        {
            const int r  = tid & 63;
            const int dq = tid >> 6;
            const float* krow = &g_k[((size_t)b * TT + k0 + r) * HH + dq * 16];
            #pragma unroll
            for (int u = 0; u < 4; u++) {
                float4 v = *(const float4*)&krow[u * 4];
                KP[(dq*16 + u*4 + 0) * 68 + r] = v.x;
                KP[(dq*16 + u*4 + 1) * 68 + r] = v.y;
                KP[(dq*16 + u*4 + 2) * 68 + r] = v.z;
                KP[(dq*16 + u*4 + 3) * 68 + r] = v.w;
            }
            const float4* vb = (const float4*)&g_v[((size_t)b * TT + k0) * HH];
            float4* vs = (float4*)Vs;
            #pragma unroll
            for (int u = 0; u < 4; u++) vs[u * 256 + tid] = vb[u * 256 + tid];
        }
        __syncthreads();

        // S = Q @ K^T  (outer-product register tile)
        float s[4][4] = {};
        #pragma unroll 16
        for (int d = 0; d < 64; d++) {
            float4 a4 = *(const float4*)&Qs[d * 64 + ty*4];
            float4 b4 = *(const float4*)&KP[d * 68 + tx*4];
            float a[4] = {a4.x, a4.y, a4.z, a4.w};
            float bb[4] = {b4.x, b4.y, b4.z, b4.w};
            #pragma unroll
            for (int i = 0; i < 4; i++)
                #pragma unroll
                for (int j = 0; j < 4; j++)
                    s[i][j] += a[i] * bb[j];
        }

        // causal mask (only the diagonal tile; k0 == q0 there)
        if (t == qt) {
            #pragma unroll
            for (int i = 0; i < 4; i++)
                #pragma unroll
                for (int j = 0; j < 4; j++)
                    if (tx*4 + j > ty*4 + i) s[i][j] = -1e30f;
        }

        // per-row tile max, reduced across the 16 tx-threads
        float mt[4];
        #pragma unroll
        for (int i = 0; i < 4; i++) {
            float v = fmaxf(fmaxf(s[i][0], s[i][1]), fmaxf(s[i][2], s[i][3]));
            v = fmaxf(v, __shfl_xor_sync(0xFFFFFFFF, v, 1));
            v = fmaxf(v, __shfl_xor_sync(0xFFFFFFFF, v, 2));
            v = fmaxf(v, __shfl_xor_sync(0xFFFFFFFF, v, 4));
            v = fmaxf(v, __shfl_xor_sync(0xFFFFFFFF, v, 8));
            mt[i] = v;
        }

        // online softmax update; s -> p
        #pragma unroll
        for (int i = 0; i < 4; i++) {
            const float mn   = fmaxf(m[i], mt[i]);
            const float corr = __expf(m[i] - mn);
            float ps = 0.f;
            #pragma unroll
            for (int j = 0; j < 4; j++) {
                float p = __expf(s[i][j] - mn);
                s[i][j] = p;
                ps += p;
            }
            ps += __shfl_xor_sync(0xFFFFFFFF, ps, 1);
            ps += __shfl_xor_sync(0xFFFFFFFF, ps, 2);
            ps += __shfl_xor_sync(0xFFFFFFFF, ps, 4);
            ps += __shfl_xor_sync(0xFFFFFFFF, ps, 8);
            l[i] = l[i] * corr + ps;
            m[i] = mn;
            #pragma unroll
            for (int n = 0; n < 4; n++) o[i][n] *= corr;
        }

        // all threads done reading K from KP before overwriting with P
        __syncthreads();

        // stage P transposed into KP: P[col j][row r]
        #pragma unroll
        for (int j = 0; j < 4; j++)
            *(float4*)&KP[(tx*4 + j) * 68 + ty*4] =
                make_float4(s[0][j], s[1][j], s[2][j], s[3][j]);
        __syncthreads();

        // O += P @ V
        #pragma unroll 16
        for (int j = 0; j < 64; j++) {
            float4 a4 = *(const float4*)&KP[j * 68 + ty*4];
            float4 b4 = *(const float4*)&Vs[j * 64 + tx*4];
            float a[4] = {a4.x, a4.y, a4.z, a4.w};
            float bb[4] = {b4.x, b4.y, b4.z, b4.w};
            #pragma unroll
            for (int i = 0; i < 4; i++)
                #pragma unroll
                for (int n = 0; n < 4; n++)
                    o[i][n] += a[i] * bb[n];
        }
        __syncthreads();
    }

    // epilogue
    #pragma unroll
    for (int i = 0; i < 4; i++) {
        const float inv = 1.f / l[i];
        float4 v = make_float4(o[i][0]*inv, o[i][1]*inv, o[i][2]*inv, o[i][3]*inv);
        *(float4*)&out[((size_t)b * TT + q0 + ty*4 + i) * HH + tx*4] = v;
    }
}

// ---------------------------------------------------------------------------
extern "C" void kernel_launch(void* const* d_in, const int* in_sizes, int n_in,
                              void* d_out, int out_size)
{
    const float* x  = (const float*)d_in[0];
    const float* Wq = (const float*)d_in[1];
    const float* Wk = (const float*)d_in[2];
    const float* Wv = (const float*)d_in[3];
    float* out = (float*)d_out;

    // idempotent, deterministic, capture-safe (not a stream op)
    cudaFuncSetAttribute(attn, cudaFuncAttributeMaxDynamicSharedMemorySize,
                         ATTN_SMEM_BYTES);

    dim3 g1(MM / 64, 3);
    qkv_gemm<<<g1, 256>>>(x, Wq, Wk, Wv);

    dim3 g2(TT / 64, BB);
    attn<<<g2, 256, ATTN_SMEM_BYTES>>>(out);
}